// round 7
// baseline (speedup 1.0000x reference)
#include <cuda_runtime.h>
#include <cstdint>
#include <float.h>

// Sparsemax, chunked tau/apply pipeline.
//
// tau pass: one 256-thread block per row, ONE streaming read; each thread
//   maintains its top-3 in registers. Support C = {x > rowmax-1} (|C|~6 for
//   Gaussian rows) is contained in the per-thread top-3 unless some thread's
//   t2 > thresh (exact ballot -> rare L2 fallback). Exact Newton/Michelot on
//   the gathered candidates gives tau.
// apply pass: out = max(x - tau[row], 0), reading x from L2 (the tau pass of
//   the SAME chunk ran in the immediately preceding launch; 32MB chunk stays
//   resident; __stcs evict-first stores protect it).
// Launches: tau(c0); fused[apply(c_i) || tau(c_{i+1})] striped by blockIdx&1
//   so DRAM read and write streams mix; apply(c_last).

#define COLS    8192
#define C4      (COLS / 4)
#define T       256
#define VPT     (C4 / T)          // 8 float4 per thread
#define CAP     768               // max pushes = 3 * 256, cannot overflow
#define CHUNK   1024              // rows per chunk (32 MB)
#define MAXROWS 8192

__device__ float g_tau[MAXROWS];

// ---------------- tau for one row ----------------
__device__ __forceinline__ void do_tau(const float* __restrict__ x, long long row)
{
    __shared__ float s_red[T / 32];
    __shared__ float s_cand[CAP];
    __shared__ int   s_cnt;
    __shared__ float s_max;
    __shared__ int   s_ovf;
    __shared__ float s_tau;
    __shared__ int   s_done;
    __shared__ float s_fb[2 * (T / 32)];

    const int tid  = threadIdx.x;
    const int lane = tid & 31;
    const int wid  = tid >> 5;
    const float4* __restrict__ xr = reinterpret_cast<const float4*>(x + row * COLS);

    if (tid == 0) { s_cnt = 0; s_ovf = 0; }

    // ---- single streaming pass: per-thread top-3 in registers ----
    float t0 = -FLT_MAX, t1 = -FLT_MAX, t2 = -FLT_MAX;
#define INS3(val) do { float _v = (val);                                  \
        if (_v > t2) {                                                    \
            if (_v > t0)      { t2 = t1; t1 = t0; t0 = _v; }              \
            else if (_v > t1) { t2 = t1; t1 = _v; }                       \
            else              { t2 = _v; }                                \
        } } while (0)
#pragma unroll
    for (int i = 0; i < VPT; ++i) {
        float4 v = xr[tid + i * T];
        INS3(v.x); INS3(v.y); INS3(v.z); INS3(v.w);
    }
#undef INS3

    // ---- block max from t0 ----
    float m = t0;
#pragma unroll
    for (int o = 16; o > 0; o >>= 1) m = fmaxf(m, __shfl_xor_sync(0xffffffffu, m, o));
    if (lane == 0) s_red[wid] = m;
    __syncthreads();
    if (wid == 0) {
        float t = (lane < T / 32) ? s_red[lane] : -FLT_MAX;
#pragma unroll
        for (int o = 4; o > 0; o >>= 1) t = fmaxf(t, __shfl_xor_sync(0xffffffffu, t, o));
        if (lane == 0) s_max = t;
    }
    __syncthreads();
    const float thresh = s_max - 1.0f;      // tau >= thresh always

    // ---- gather candidates from registers; overflow if t2 beats thresh ----
    if (t0 > thresh) { int q = atomicAdd(&s_cnt, 1); s_cand[q] = t0; }
    if (t1 > thresh) { int q = atomicAdd(&s_cnt, 1); s_cand[q] = t1; }
    if (t2 > thresh) { int q = atomicAdd(&s_cnt, 1); s_cand[q] = t2; s_ovf = 1; }
    __syncthreads();

    if (!s_ovf) {
        // ---- exact Newton/Michelot on tiny candidate set (warp 0) ----
        if (wid == 0) {
            const int cnt = s_cnt;
            float tau = thresh;
#pragma unroll 1
            for (int it = 0; it < 64; ++it) {
                float s = 0.0f, k = 0.0f;
                for (int i = lane; i < cnt; i += 32) {
                    float c = s_cand[i];
                    if (c > tau) { s += c; k += 1.0f; }
                }
#pragma unroll
                for (int o = 16; o > 0; o >>= 1) {
                    s += __shfl_xor_sync(0xffffffffu, s, o);
                    k += __shfl_xor_sync(0xffffffffu, k, o);
                }
                if (k < 0.5f) break;          // safety (cannot happen in theory)
                float nt = (s - 1.0f) / k;
                if (nt == tau) break;         // exact fixed point
                tau = nt;
            }
            if (lane == 0) g_tau[row] = tau;
        }
    } else {
        // ---- rare fallback: block Michelot over the row (L2-resident) ----
        float tau = thresh;
#pragma unroll 1
        for (int it = 0; it < 64; ++it) {
            float s = 0.0f, k = 0.0f;
#pragma unroll
            for (int i = 0; i < VPT; ++i) {
                float4 v = xr[tid + i * T];
                if (v.x > tau) { s += v.x; k += 1.0f; }
                if (v.y > tau) { s += v.y; k += 1.0f; }
                if (v.z > tau) { s += v.z; k += 1.0f; }
                if (v.w > tau) { s += v.w; k += 1.0f; }
            }
#pragma unroll
            for (int o = 16; o > 0; o >>= 1) {
                s += __shfl_xor_sync(0xffffffffu, s, o);
                k += __shfl_xor_sync(0xffffffffu, k, o);
            }
            if (lane == 0) { s_fb[2 * wid] = s; s_fb[2 * wid + 1] = k; }
            __syncthreads();
            if (tid == 0) {
                float Sx = 0.0f, K = 0.0f;
                for (int w = 0; w < T / 32; ++w) { Sx += s_fb[2 * w]; K += s_fb[2 * w + 1]; }
                float nt = (K < 0.5f) ? tau : (Sx - 1.0f) / K;
                s_done = (nt == tau) || (K < 0.5f);
                s_tau  = nt;
            }
            __syncthreads();
            tau = s_tau;
            if (s_done) break;
        }
        if (tid == 0) g_tau[row] = tau;
    }
}

// ---------------- apply for one row ----------------
__device__ __forceinline__ void do_apply(const float* __restrict__ x,
                                         float* __restrict__ out, long long row)
{
    const float tau = g_tau[row];
    const float4* __restrict__ xr = reinterpret_cast<const float4*>(x + row * COLS);
    float4* __restrict__ yr       = reinterpret_cast<float4*>(out + row * COLS);
#pragma unroll
    for (int i = 0; i < VPT; ++i) {
        float4 v = xr[threadIdx.x + i * T];
        float4 r;
        r.x = fmaxf(v.x - tau, 0.0f);
        r.y = fmaxf(v.y - tau, 0.0f);
        r.z = fmaxf(v.z - tau, 0.0f);
        r.w = fmaxf(v.w - tau, 0.0f);
        __stcs(yr + threadIdx.x + i * T, r);   // evict-first: keep x chunk in L2
    }
}

// ---------------- kernels ----------------
__global__ __launch_bounds__(T)
void k_tau(const float* __restrict__ x, int base, int n)
{
    if ((int)blockIdx.x < n) do_tau(x, (long long)base + blockIdx.x);
}

__global__ __launch_bounds__(T)
void k_apply(const float* __restrict__ x, float* __restrict__ out, int base, int n)
{
    if ((int)blockIdx.x < n) do_apply(x, out, (long long)base + blockIdx.x);
}

// apply(chunk c) co-scheduled with tau(chunk c+1), roles striped by blockIdx&1
__global__ __launch_bounds__(T)
void k_fused(const float* __restrict__ x, float* __restrict__ out,
             int apply_base, int napply, int tau_base, int ntau)
{
    const int b = blockIdx.x;
    const int nmin = (napply < ntau) ? napply : ntau;
    const int half = 2 * nmin;
    if (b < half) {
        if (b & 1) do_tau(x, (long long)tau_base + (b >> 1));
        else       do_apply(x, out, (long long)apply_base + (b >> 1));
    } else {
        const int r = b - half;
        if (napply > ntau) { if (r < napply - ntau) do_apply(x, out, (long long)apply_base + nmin + r); }
        else               { if (r < ntau - napply) do_tau(x, (long long)tau_base + nmin + r); }
    }
}

extern "C" void kernel_launch(void* const* d_in, const int* in_sizes, int n_in,
                              void* d_out, int out_size)
{
    const float* x = (const float*)d_in[0];
    float* out     = (float*)d_out;
    const int rows = in_sizes[0] / COLS;

    const int nc = (rows + CHUNK - 1) / CHUNK;
    auto csize = [&](int c) {
        int s = rows - c * CHUNK;
        return (s > CHUNK) ? CHUNK : s;
    };

    if (nc <= 1) {
        k_tau<<<rows, T>>>(x, 0, rows);
        k_apply<<<rows, T>>>(x, out, 0, rows);
        return;
    }

    k_tau<<<csize(0), T>>>(x, 0, csize(0));
    for (int c = 0; c + 1 < nc; ++c) {
        const int na = csize(c), nt = csize(c + 1);
        k_fused<<<na + nt, T>>>(x, out, c * CHUNK, na, (c + 1) * CHUNK, nt);
    }
    const int last = nc - 1;
    k_apply<<<csize(last), T>>>(x, out, last * CHUNK, csize(last));
}

// round 8
// speedup vs baseline: 1.2484x; 1.2484x over previous
#include <cuda_runtime.h>
#include <cstdint>
#include <float.h>

// Sparsemax, one 256-thread block per row, single kernel.
//
// Pass A: stream the row from DRAM once; each thread keeps its top-3 in
//   registers. Support C = {x > rowmax-1} (|C| ~ 6 for Gaussian rows) is
//   contained in the per-thread top-3 unless some thread's t2 > thresh
//   (exact detection -> rare fallback that re-reads the row from L2).
// Solve: exact Newton/Michelot on the gathered candidates, run redundantly
//   by every warp (no broadcast barrier).
// Pass B: re-read own row (guaranteed L2 hit -- the block streamed it
//   microseconds ago; ~38 MB of in-flight rows << 126 MB L2) and emit
//   max(x - tau, 0) with evict-first stores.
// DRAM traffic = 256 MB minimum; the re-read rides on L2.

#define COLS 8192
#define C4   (COLS / 4)
#define T    256
#define VPT  (C4 / T)             // 8 float4 per thread
#define CAP  768                  // 3 pushes x 256 threads, cannot overflow

__global__ __launch_bounds__(T)
void sparsemax_fused(const float* __restrict__ x, float* __restrict__ out, int rows)
{
    __shared__ float s_red[T / 32];
    __shared__ float s_cand[CAP];
    __shared__ int   s_cnt;
    __shared__ float s_max;
    __shared__ int   s_ovf;
    __shared__ float s_tau;
    __shared__ int   s_done;
    __shared__ float s_fb[2 * (T / 32)];

    const int tid  = threadIdx.x;
    const int lane = tid & 31;
    const int wid  = tid >> 5;
    const long long row = blockIdx.x;
    if (row >= rows) return;

    const float4* __restrict__ xr = reinterpret_cast<const float4*>(x + row * COLS);

    if (tid == 0) { s_cnt = 0; s_ovf = 0; }

    // ---- pass A: single DRAM stream, per-thread top-3 in registers ----
    float t0 = -FLT_MAX, t1 = -FLT_MAX, t2 = -FLT_MAX;
#define INS3(val) do { float _v = (val);                                  \
        if (_v > t2) {                                                    \
            if (_v > t0)      { t2 = t1; t1 = t0; t0 = _v; }              \
            else if (_v > t1) { t2 = t1; t1 = _v; }                       \
            else              { t2 = _v; }                                \
        } } while (0)
#pragma unroll
    for (int i = 0; i < VPT; ++i) {
        float4 v = xr[tid + i * T];
        INS3(v.x); INS3(v.y); INS3(v.z); INS3(v.w);
    }
#undef INS3

    // ---- block max (from per-thread t0) ----
    float m = t0;
#pragma unroll
    for (int o = 16; o > 0; o >>= 1) m = fmaxf(m, __shfl_xor_sync(0xffffffffu, m, o));
    if (lane == 0) s_red[wid] = m;
    __syncthreads();                                   // also covers s_cnt init
    if (wid == 0) {
        float t = (lane < T / 32) ? s_red[lane] : -FLT_MAX;
#pragma unroll
        for (int o = 4; o > 0; o >>= 1) t = fmaxf(t, __shfl_xor_sync(0xffffffffu, t, o));
        if (lane == 0) s_max = t;
    }
    __syncthreads();
    const float thresh = s_max - 1.0f;                 // tau >= thresh always

    // ---- gather candidates from registers; overflow iff t2 > thresh ----
    if (t0 > thresh) { int q = atomicAdd(&s_cnt, 1); s_cand[q] = t0; }
    if (t1 > thresh) { int q = atomicAdd(&s_cnt, 1); s_cand[q] = t1; }
    if (t2 > thresh) { int q = atomicAdd(&s_cnt, 1); s_cand[q] = t2; s_ovf = 1; }
    __syncthreads();

    float tau;
    if (!s_ovf) {
        // ---- exact Newton/Michelot on tiny candidate set, ALL warps
        //      redundantly (same data -> same tau; no broadcast barrier) ----
        const int cnt = s_cnt;
        float tt = thresh;
#pragma unroll 1
        for (int it = 0; it < 64; ++it) {
            float s = 0.0f, k = 0.0f;
            for (int i = lane; i < cnt; i += 32) {
                float c = s_cand[i];
                if (c > tt) { s += c; k += 1.0f; }
            }
#pragma unroll
            for (int o = 16; o > 0; o >>= 1) {
                s += __shfl_xor_sync(0xffffffffu, s, o);
                k += __shfl_xor_sync(0xffffffffu, k, o);
            }
            if (k < 0.5f) break;              // safety (cannot happen in theory)
            float nt = (s - 1.0f) / k;
            if (nt == tt) break;              // exact fixed point
            tt = nt;
        }
        tau = tt;
    } else {
        // ---- rare fallback: block Michelot over the row (L2-resident) ----
        float tt = thresh;
#pragma unroll 1
        for (int it = 0; it < 64; ++it) {
            float s = 0.0f, k = 0.0f;
#pragma unroll 1
            for (int i = 0; i < VPT; ++i) {
                float4 v = xr[tid + i * T];
                if (v.x > tt) { s += v.x; k += 1.0f; }
                if (v.y > tt) { s += v.y; k += 1.0f; }
                if (v.z > tt) { s += v.z; k += 1.0f; }
                if (v.w > tt) { s += v.w; k += 1.0f; }
            }
#pragma unroll
            for (int o = 16; o > 0; o >>= 1) {
                s += __shfl_xor_sync(0xffffffffu, s, o);
                k += __shfl_xor_sync(0xffffffffu, k, o);
            }
            if (lane == 0) { s_fb[2 * wid] = s; s_fb[2 * wid + 1] = k; }
            __syncthreads();
            if (tid == 0) {
                float Sx = 0.0f, K = 0.0f;
                for (int w = 0; w < T / 32; ++w) { Sx += s_fb[2 * w]; K += s_fb[2 * w + 1]; }
                float nt = (K < 0.5f) ? tt : (Sx - 1.0f) / K;
                s_done = (nt == tt) || (K < 0.5f);
                s_tau  = nt;
            }
            __syncthreads();
            tt = s_tau;
            if (s_done) break;
        }
        tau = tt;
    }

    // ---- pass B: re-read own row (L2 hit), emit output ----
    float4* __restrict__ yr = reinterpret_cast<float4*>(out + row * COLS);
#pragma unroll
    for (int i = 0; i < VPT; ++i) {
        float4 v = xr[tid + i * T];
        float4 r;
        r.x = fmaxf(v.x - tau, 0.0f);
        r.y = fmaxf(v.y - tau, 0.0f);
        r.z = fmaxf(v.z - tau, 0.0f);
        r.w = fmaxf(v.w - tau, 0.0f);
        __stcs(yr + tid + i * T, r);
    }
}

extern "C" void kernel_launch(void* const* d_in, const int* in_sizes, int n_in,
                              void* d_out, int out_size)
{
    const float* x = (const float*)d_in[0];
    float* out     = (float*)d_out;
    const int rows = in_sizes[0] / COLS;
    sparsemax_fused<<<rows, T>>>(x, out, rows);
}

// round 9
// speedup vs baseline: 1.4802x; 1.1856x over previous
#include <cuda_runtime.h>
#include <cstdint>
#include <float.h>

// Sparsemax, one 256-thread block per row, three light passes.
//
// Pass A: stream row from DRAM, max only (4 independent fmax accumulators,
//         no serial chain, no per-thread top-k state -> low regs, high occ).
// Pass B: re-read own row from L2 (guaranteed hit: the block streamed it
//         microseconds ago; in-flight rows << 126 MB L2), gather the
//         candidates > rowmax-1 into smem. Support of sparsemax is always
//         contained there (tau >= rowmax - 1); |C| ~ 6 for Gaussian rows.
// Solve:  exact Newton/Michelot on the candidates, run redundantly by every
//         warp (no broadcast barrier).
// Pass C: re-read from L2 (last use, evict-first) and emit max(x-tau, 0)
//         with streaming stores.
// DRAM traffic = 256 MB minimum; passes B/C ride on L2.

#define COLS 8192
#define C4   (COLS / 4)
#define T    256
#define VPT  (C4 / T)             // 8 float4 per thread
#define CAP  1024                 // candidate buffer (|C| ~ 6 expected)

__global__ __launch_bounds__(T, 6)
void sparsemax3(const float* __restrict__ x, float* __restrict__ out, int rows)
{
    __shared__ float s_red[T / 32];
    __shared__ float s_cand[CAP];
    __shared__ int   s_cnt;
    __shared__ float s_max;
    __shared__ float s_tau;
    __shared__ int   s_done;
    __shared__ float s_fb[2 * (T / 32)];

    const int tid  = threadIdx.x;
    const int lane = tid & 31;
    const int wid  = tid >> 5;
    const long long row = blockIdx.x;
    if (row >= rows) return;

    const float4* __restrict__ xr = reinterpret_cast<const float4*>(x + row * COLS);

    if (tid == 0) s_cnt = 0;

    // ---- pass A: DRAM stream, max only (4 independent chains) ----
    float m0 = -FLT_MAX, m1 = -FLT_MAX, m2 = -FLT_MAX, m3 = -FLT_MAX;
#pragma unroll
    for (int i = 0; i < VPT; ++i) {
        float4 v = xr[tid + i * T];
        m0 = fmaxf(m0, v.x);
        m1 = fmaxf(m1, v.y);
        m2 = fmaxf(m2, v.z);
        m3 = fmaxf(m3, v.w);
    }
    float m = fmaxf(fmaxf(m0, m1), fmaxf(m2, m3));
#pragma unroll
    for (int o = 16; o > 0; o >>= 1) m = fmaxf(m, __shfl_xor_sync(0xffffffffu, m, o));
    if (lane == 0) s_red[wid] = m;
    __syncthreads();                                   // also covers s_cnt init
    if (wid == 0) {
        float t = (lane < T / 32) ? s_red[lane] : -FLT_MAX;
#pragma unroll
        for (int o = 4; o > 0; o >>= 1) t = fmaxf(t, __shfl_xor_sync(0xffffffffu, t, o));
        if (lane == 0) s_max = t;
    }
    __syncthreads();
    const float thresh = s_max - 1.0f;                 // tau >= thresh always

    // ---- pass B: gather candidates > thresh (row is L2-resident) ----
#pragma unroll
    for (int i = 0; i < VPT; ++i) {
        float4 v = xr[tid + i * T];
        if (v.x > thresh) { int q = atomicAdd(&s_cnt, 1); if (q < CAP) s_cand[q] = v.x; }
        if (v.y > thresh) { int q = atomicAdd(&s_cnt, 1); if (q < CAP) s_cand[q] = v.y; }
        if (v.z > thresh) { int q = atomicAdd(&s_cnt, 1); if (q < CAP) s_cand[q] = v.z; }
        if (v.w > thresh) { int q = atomicAdd(&s_cnt, 1); if (q < CAP) s_cand[q] = v.w; }
    }
    __syncthreads();
    const int cnt = s_cnt;

    float tau;
    if (cnt <= CAP) {
        // ---- exact Newton/Michelot on tiny candidate set, ALL warps
        //      redundantly (same data -> same tau; no broadcast barrier) ----
        float tt = thresh;
#pragma unroll 1
        for (int it = 0; it < 64; ++it) {
            float s = 0.0f, k = 0.0f;
            for (int i = lane; i < cnt; i += 32) {
                float c = s_cand[i];
                if (c > tt) { s += c; k += 1.0f; }
            }
#pragma unroll
            for (int o = 16; o > 0; o >>= 1) {
                s += __shfl_xor_sync(0xffffffffu, s, o);
                k += __shfl_xor_sync(0xffffffffu, k, o);
            }
            if (k < 0.5f) break;              // safety (cannot happen in theory)
            float nt = (s - 1.0f) / k;
            if (nt == tt) break;              // exact fixed point
            tt = nt;
        }
        tau = tt;
    } else {
        // ---- pathological fallback: block Michelot over L2-resident row ----
        float tt = thresh;
#pragma unroll 1
        for (int it = 0; it < 64; ++it) {
            float s = 0.0f, k = 0.0f;
#pragma unroll 1
            for (int i = 0; i < VPT; ++i) {
                float4 v = xr[tid + i * T];
                if (v.x > tt) { s += v.x; k += 1.0f; }
                if (v.y > tt) { s += v.y; k += 1.0f; }
                if (v.z > tt) { s += v.z; k += 1.0f; }
                if (v.w > tt) { s += v.w; k += 1.0f; }
            }
#pragma unroll
            for (int o = 16; o > 0; o >>= 1) {
                s += __shfl_xor_sync(0xffffffffu, s, o);
                k += __shfl_xor_sync(0xffffffffu, k, o);
            }
            if (lane == 0) { s_fb[2 * wid] = s; s_fb[2 * wid + 1] = k; }
            __syncthreads();
            if (tid == 0) {
                float Sx = 0.0f, K = 0.0f;
                for (int w = 0; w < T / 32; ++w) { Sx += s_fb[2 * w]; K += s_fb[2 * w + 1]; }
                float nt = (K < 0.5f) ? tt : (Sx - 1.0f) / K;
                s_done = (nt == tt) || (K < 0.5f);
                s_tau  = nt;
            }
            __syncthreads();
            tt = s_tau;
            if (s_done) break;
        }
        tau = tt;
    }

    // ---- pass C: last read (L2 hit, evict after), emit output ----
    float4* __restrict__ yr = reinterpret_cast<float4*>(out + row * COLS);
#pragma unroll
    for (int i = 0; i < VPT; ++i) {
        float4 v = __ldcs(xr + tid + i * T);
        float4 r;
        r.x = fmaxf(v.x - tau, 0.0f);
        r.y = fmaxf(v.y - tau, 0.0f);
        r.z = fmaxf(v.z - tau, 0.0f);
        r.w = fmaxf(v.w - tau, 0.0f);
        __stcs(yr + tid + i * T, r);
    }
}

extern "C" void kernel_launch(void* const* d_in, const int* in_sizes, int n_in,
                              void* d_out, int out_size)
{
    const float* x = (const float*)d_in[0];
    float* out     = (float*)d_out;
    const int rows = in_sizes[0] / COLS;
    sparsemax3<<<rows, T>>>(x, out, rows);
}